// round 14
// baseline (speedup 1.0000x reference)
#include <cuda_runtime.h>
#include <cstdint>

// CommunicationLayer: out[a] = x[a] + b + ((sum_j x[j] - x[a]) / 2) @ W
// A=3, D=128, fp32. Persistent-CTA TF32 tensor-core kernel, cp.async pipelined.
//
// Algebra: msg[a] = Q[a1] + Q[a2] where Q[j] = x[j] @ (0.5*W)  (0.5 folded into W,
// exact). x tiles stay exact fp32 in smem (residual path untouched); tf32
// rounding (cvt.rna) applied only at A-fragment load time.

#define AGENTS  3
#define DDIM    128
#define TILE_M  32
#define NTH     256
#define STAGES  3

#define SXT_STRIDE   132                              // padded x-tile row (floats)
#define STAGE_FLOATS (AGENTS * TILE_M * SXT_STRIDE)   // 12672
#define SW_STRIDE    136                              // padded W row (floats)
#define SW_FLOATS    (DDIM * SW_STRIDE)               // 17408
#define SW_OFF       (STAGES * STAGE_FLOATS)          // 38016
#define SB_OFF       (SW_OFF + SW_FLOATS)             // 55424
#define SMEM_FLOATS  (SB_OFF + DDIM)                  // 55552
#define SMEM_BYTES   (SMEM_FLOATS * 4)                // 222208

__device__ __forceinline__ uint32_t f2tf32(float f) {
    uint32_t r;
    asm("cvt.rna.tf32.f32 %0, %1;" : "=r"(r) : "f"(f));
    return r;
}

__device__ __forceinline__ void mma_tf32(float c[4], const uint32_t a[4], const uint32_t b[2]) {
    asm volatile(
        "mma.sync.aligned.m16n8k8.row.col.f32.tf32.tf32.f32 "
        "{%0,%1,%2,%3}, {%4,%5,%6,%7}, {%8,%9}, {%0,%1,%2,%3};"
        : "+f"(c[0]), "+f"(c[1]), "+f"(c[2]), "+f"(c[3])
        : "r"(a[0]), "r"(a[1]), "r"(a[2]), "r"(a[3]),
          "r"(b[0]), "r"(b[1]));
}

__device__ __forceinline__ void cp_async16(float* dst_smem, const float* src_gmem) {
    uint32_t d = (uint32_t)__cvta_generic_to_shared(dst_smem);
    asm volatile("cp.async.cg.shared.global [%0], [%1], 16;\n" :: "r"(d), "l"(src_gmem));
}

// Prefetch one full x tile (3 agents x 32 x 128 fp32) into stage s.
__device__ __forceinline__ void prefetch_tile(float* stage, const float* __restrict__ X,
                                              int t, int ntiles, int nB, int tid) {
    if (t < ntiles) {
        const long long tb = (long long)t * TILE_M * DDIM;
        #pragma unroll
        for (int q = 0; q < 12; q++) {
            int idx = tid + q * NTH;            // 0..3071 float4s
            int a   = idx >> 10;                // 1024 float4 per agent tile
            int rem = idx & 1023;
            int r   = rem >> 5;                 // 32 float4 per row
            int c   = (rem & 31) << 2;          // float col
            const float* src = X + (long long)a * nB * DDIM + tb + r * DDIM + c;
            float*       dst = stage + a * TILE_M * SXT_STRIDE + r * SXT_STRIDE + c;
            cp_async16(dst, src);
        }
    }
    asm volatile("cp.async.commit_group;\n" ::: "memory");
}

__global__ __launch_bounds__(NTH, 1)
void comm_layer_kernel(const float* __restrict__ X,    // [3, B, 128]
                       const float* __restrict__ W,    // [128, 128]
                       const float* __restrict__ bias, // [128]
                       float* __restrict__ out,        // [3, B, 128]
                       int nB, int ntiles)
{
    extern __shared__ float smem[];
    float* sW = smem + SW_OFF;     // tf32(0.5*W), [128][136]
    float* sB = smem + SB_OFF;

    const int tid  = threadIdx.x;
    const int warp = tid >> 5, lane = tid & 31;
    const int wm   = warp >> 2;    // 0..1 : 16-row m block
    const int wn   = warp & 3;     // 0..3 : 32-col n block
    const int gid  = lane >> 2;    // 0..7
    const int tig  = lane & 3;     // 0..3

    // ---- prologue: kick off the first STAGES tile prefetches immediately ----
    #pragma unroll
    for (int s = 0; s < STAGES; s++)
        prefetch_tile(smem + s * STAGE_FLOATS, X,
                      blockIdx.x + s * (int)gridDim.x, ntiles, nB, tid);

    // ---- load W (scaled by 0.5, tf32-rounded) + bias, once per CTA ----
    for (int i = tid; i < (DDIM * DDIM) / 4; i += NTH) {
        float4 v = __ldg(((const float4*)W) + i);
        int r = i >> 5, c = (i & 31) << 2;
        float* d = sW + r * SW_STRIDE + c;
        d[0] = __uint_as_float(f2tf32(0.5f * v.x));
        d[1] = __uint_as_float(f2tf32(0.5f * v.y));
        d[2] = __uint_as_float(f2tf32(0.5f * v.z));
        d[3] = __uint_as_float(f2tf32(0.5f * v.w));
    }
    if (tid < DDIM) sB[tid] = bias[tid];
    __syncthreads();

    // bias hoisted into registers (fixed columns per thread)
    float br[4][2];
    #pragma unroll
    for (int ni = 0; ni < 4; ni++) {
        int c0 = wn * 32 + ni * 8 + 2 * tig;
        br[ni][0] = sB[c0];
        br[ni][1] = sB[c0 + 1];
    }

    // per-thread fragment base offsets
    const int a_base = (wm * 16 + gid) * SXT_STRIDE + tig;   // + j*tile + k0
    const int b_base = tig * SW_STRIDE + wn * 32 + gid;      // + k0*stride + ni*8

    // ---- main pipelined loop over tiles ----
    int iter = 0;
    for (int t = blockIdx.x; t < ntiles; t += (int)gridDim.x, iter++) {
        const int s = iter % STAGES;
        asm volatile("cp.async.wait_group %0;\n" :: "n"(STAGES - 1) : "memory");
        __syncthreads();

        const float* sx = smem + s * STAGE_FLOATS;

        // Q[j] = x[j] @ (0.5*W) for j = 0..2, accumulated in fp32
        float acc[AGENTS][4][4];
        #pragma unroll
        for (int j = 0; j < AGENTS; j++)
            #pragma unroll
            for (int ni = 0; ni < 4; ni++)
                #pragma unroll
                for (int e = 0; e < 4; e++)
                    acc[j][ni][e] = 0.0f;

        #pragma unroll
        for (int k0 = 0; k0 < DDIM; k0 += 8) {
            // B fragments: shared across all 3 agents this k-step
            uint32_t bfr[4][2];
            #pragma unroll
            for (int ni = 0; ni < 4; ni++) {
                const float* pw = sW + k0 * SW_STRIDE + b_base + ni * 8;
                bfr[ni][0] = __float_as_uint(pw[0]);
                bfr[ni][1] = __float_as_uint(pw[4 * SW_STRIDE]);
            }
            #pragma unroll
            for (int j = 0; j < AGENTS; j++) {
                const float* pm = sx + j * TILE_M * SXT_STRIDE + a_base + k0;
                uint32_t afr[4];
                afr[0] = f2tf32(pm[0]);
                afr[1] = f2tf32(pm[8 * SXT_STRIDE]);
                afr[2] = f2tf32(pm[4]);
                afr[3] = f2tf32(pm[8 * SXT_STRIDE + 4]);
                #pragma unroll
                for (int ni = 0; ni < 4; ni++)
                    mma_tf32(acc[j][ni], afr, bfr[ni]);
            }
        }

        // ---- epilogue: out[a] = x[a] + bias + Q[a1] + Q[a2] ----
        const long long tb = (long long)t * TILE_M * DDIM;
        #pragma unroll
        for (int a = 0; a < AGENTS; a++) {
            const int a1 = (a + 1) % 3, a2 = (a + 2) % 3;
            const float* sxa = sx + a * TILE_M * SXT_STRIDE;
            float* oa = out + (long long)a * nB * DDIM + tb;
            #pragma unroll
            for (int ni = 0; ni < 4; ni++) {
                const int c0 = wn * 32 + ni * 8 + 2 * tig;
                const int r0 = wm * 16 + gid;
                float2 xv0 = *(const float2*)(sxa + r0 * SXT_STRIDE + c0);
                float2 o0;
                o0.x = xv0.x + br[ni][0] + acc[a1][ni][0] + acc[a2][ni][0];
                o0.y = xv0.y + br[ni][1] + acc[a1][ni][1] + acc[a2][ni][1];
                *(float2*)(oa + (long long)r0 * DDIM + c0) = o0;

                const int r1 = r0 + 8;
                float2 xv1 = *(const float2*)(sxa + r1 * SXT_STRIDE + c0);
                float2 o1;
                o1.x = xv1.x + br[ni][0] + acc[a1][ni][2] + acc[a2][ni][2];
                o1.y = xv1.y + br[ni][1] + acc[a1][ni][3] + acc[a2][ni][3];
                *(float2*)(oa + (long long)r1 * DDIM + c0) = o1;
            }
        }
        __syncthreads();   // everyone done reading stage s

        // refill stage s with tile t + STAGES*grid
        prefetch_tile(smem + s * STAGE_FLOATS, X,
                      t + STAGES * (int)gridDim.x, ntiles, nB, tid);
    }
}

extern "C" void kernel_launch(void* const* d_in, const int* in_sizes, int n_in,
                              void* d_out, int out_size)
{
    const float* X    = (const float*)d_in[0];   // [3, B, 128]
    const float* W    = (const float*)d_in[1];   // [128, 128]
    const float* bias = (const float*)d_in[2];   // [128]
    float* out = (float*)d_out;

    const int nB     = in_sizes[0] / (AGENTS * DDIM);   // 524288
    const int ntiles = nB / TILE_M;                     // 16384

    int dev = 0, nsm = 148;
    cudaGetDevice(&dev);
    cudaDeviceGetAttribute(&nsm, cudaDevAttrMultiProcessorCount, dev);

    cudaFuncSetAttribute(comm_layer_kernel,
                         cudaFuncAttributeMaxDynamicSharedMemorySize, SMEM_BYTES);
    comm_layer_kernel<<<nsm, NTH, SMEM_BYTES>>>(X, W, bias, out, nB, ntiles);
}

// round 15
// speedup vs baseline: 1.1116x; 1.1116x over previous
#include <cuda_runtime.h>
#include <cstdint>

// CommunicationLayer: out[a] = x[a] + b + ((sum_j x[j] - x[a]) / 2) @ W
// A=3, D=128, fp32. Persistent-CTA TF32 mma.sync kernel, cp.async pipelined.
//
// R14: W fragments hoisted into REGISTERS (128 regs/thread, loaded once per
// kernel) -> zero B-operand smem traffic in the main loop. A operands use raw
// fp32 bits (HW truncates to tf32); 0.5 folded into W (exact).

#define AGENTS  3
#define DDIM    128
#define TILE_M  32
#define NTH     256
#define STAGES  3

#define SXT_STRIDE   132                              // padded x-tile row (floats)
#define STAGE_FLOATS (AGENTS * TILE_M * SXT_STRIDE)   // 12672
#define SW_STRIDE    136                              // padded W row (floats)
#define SW_FLOATS    (DDIM * SW_STRIDE)               // 17408
#define SW_OFF       (STAGES * STAGE_FLOATS)          // 38016
#define SB_OFF       (SW_OFF + SW_FLOATS)
#define SMEM_FLOATS  (SB_OFF + DDIM)
#define SMEM_BYTES   (SMEM_FLOATS * 4)                // 222208

__device__ __forceinline__ uint32_t f2tf32(float f) {
    uint32_t r;
    asm("cvt.rna.tf32.f32 %0, %1;" : "=r"(r) : "f"(f));
    return r;
}

__device__ __forceinline__ void mma_tf32(float c[4], const uint32_t a[4], const uint32_t b0, const uint32_t b1) {
    asm volatile(
        "mma.sync.aligned.m16n8k8.row.col.f32.tf32.tf32.f32 "
        "{%0,%1,%2,%3}, {%4,%5,%6,%7}, {%8,%9}, {%0,%1,%2,%3};"
        : "+f"(c[0]), "+f"(c[1]), "+f"(c[2]), "+f"(c[3])
        : "r"(a[0]), "r"(a[1]), "r"(a[2]), "r"(a[3]),
          "r"(b0), "r"(b1));
}

__device__ __forceinline__ void cp_async16(float* dst_smem, const float* src_gmem) {
    uint32_t d = (uint32_t)__cvta_generic_to_shared(dst_smem);
    asm volatile("cp.async.cg.shared.global [%0], [%1], 16;\n" :: "r"(d), "l"(src_gmem));
}

// Prefetch one full x tile (3 agents x 32 x 128 fp32) into stage s.
__device__ __forceinline__ void prefetch_tile(float* stage, const float* __restrict__ X,
                                              int t, int ntiles, int nB, int tid) {
    if (t < ntiles) {
        const long long tb = (long long)t * TILE_M * DDIM;
        #pragma unroll
        for (int q = 0; q < 12; q++) {
            int idx = tid + q * NTH;            // 0..3071 float4s
            int a   = idx >> 10;                // 1024 float4 per agent tile
            int rem = idx & 1023;
            int r   = rem >> 5;                 // 32 float4 per row
            int c   = (rem & 31) << 2;          // float col
            const float* src = X + (long long)a * nB * DDIM + tb + r * DDIM + c;
            float*       dst = stage + a * TILE_M * SXT_STRIDE + r * SXT_STRIDE + c;
            cp_async16(dst, src);
        }
    }
    asm volatile("cp.async.commit_group;\n" ::: "memory");
}

__global__ __launch_bounds__(NTH, 1)
void comm_layer_kernel(const float* __restrict__ X,    // [3, B, 128]
                       const float* __restrict__ W,    // [128, 128]
                       const float* __restrict__ bias, // [128]
                       float* __restrict__ out,        // [3, B, 128]
                       int nB, int ntiles)
{
    extern __shared__ float smem[];
    float* sW = smem + SW_OFF;     // tf32(0.5*W), [128][136] (used only at init)
    float* sB = smem + SB_OFF;

    const int tid  = threadIdx.x;
    const int warp = tid >> 5, lane = tid & 31;
    const int wm   = warp >> 2;    // 0..1 : 16-row m block
    const int wn   = warp & 3;     // 0..3 : 32-col n block
    const int gid  = lane >> 2;    // 0..7
    const int tig  = lane & 3;     // 0..3

    // ---- prologue: kick off the first STAGES tile prefetches immediately ----
    #pragma unroll
    for (int s = 0; s < STAGES; s++)
        prefetch_tile(smem + s * STAGE_FLOATS, X,
                      blockIdx.x + s * (int)gridDim.x, ntiles, nB, tid);

    // ---- stage W (scaled by 0.5, tf32 RNA-rounded) + bias into smem ----
    for (int i = tid; i < (DDIM * DDIM) / 4; i += NTH) {
        float4 v = __ldg(((const float4*)W) + i);
        int r = i >> 5, c = (i & 31) << 2;
        float* d = sW + r * SW_STRIDE + c;
        d[0] = __uint_as_float(f2tf32(0.5f * v.x));
        d[1] = __uint_as_float(f2tf32(0.5f * v.y));
        d[2] = __uint_as_float(f2tf32(0.5f * v.z));
        d[3] = __uint_as_float(f2tf32(0.5f * v.w));
    }
    if (tid < DDIM) sB[tid] = bias[tid];
    __syncthreads();

    // ---- hoist ALL B fragments for this thread into registers (once) ----
    // breg[k-step][ni][pair]: W[k0+tig][col], W[k0+tig+4][col], col = wn*32+ni*8+gid
    uint32_t breg[16][4][2];
    {
        const float* wb = sW + tig * SW_STRIDE + wn * 32 + gid;
        #pragma unroll
        for (int kk = 0; kk < 16; kk++) {
            #pragma unroll
            for (int ni = 0; ni < 4; ni++) {
                const float* pw = wb + (kk * 8) * SW_STRIDE + ni * 8;
                breg[kk][ni][0] = __float_as_uint(pw[0]);
                breg[kk][ni][1] = __float_as_uint(pw[4 * SW_STRIDE]);
            }
        }
    }

    // bias hoisted into registers (fixed columns per thread)
    float br[4][2];
    #pragma unroll
    for (int ni = 0; ni < 4; ni++) {
        int c0 = wn * 32 + ni * 8 + 2 * tig;
        br[ni][0] = sB[c0];
        br[ni][1] = sB[c0 + 1];
    }

    // per-thread A fragment base offset
    const int a_base = (wm * 16 + gid) * SXT_STRIDE + tig;   // + j*tile + k0

    // ---- main pipelined loop over tiles ----
    int iter = 0;
    for (int t = blockIdx.x; t < ntiles; t += (int)gridDim.x, iter++) {
        const int s = iter % STAGES;
        asm volatile("cp.async.wait_group %0;\n" :: "n"(STAGES - 1) : "memory");
        __syncthreads();

        const float* sx = smem + s * STAGE_FLOATS;

        // Q[j] = x[j] @ (0.5*W) for j = 0..2, fp32 accumulate.
        // A operands: raw fp32 bits (HW uses top 19 bits => tf32-truncate).
        float acc[AGENTS][4][4];
        #pragma unroll
        for (int j = 0; j < AGENTS; j++)
            #pragma unroll
            for (int ni = 0; ni < 4; ni++)
                #pragma unroll
                for (int e = 0; e < 4; e++)
                    acc[j][ni][e] = 0.0f;

        #pragma unroll
        for (int kk = 0; kk < 16; kk++) {
            const int k0 = kk * 8;
            #pragma unroll
            for (int j = 0; j < AGENTS; j++) {
                const float* pm = sx + j * TILE_M * SXT_STRIDE + a_base + k0;
                uint32_t afr[4];
                afr[0] = __float_as_uint(pm[0]);
                afr[1] = __float_as_uint(pm[8 * SXT_STRIDE]);
                afr[2] = __float_as_uint(pm[4]);
                afr[3] = __float_as_uint(pm[8 * SXT_STRIDE + 4]);
                #pragma unroll
                for (int ni = 0; ni < 4; ni++)
                    mma_tf32(acc[j][ni], afr, breg[kk][ni][0], breg[kk][ni][1]);
            }
        }

        // ---- epilogue: out[a] = x[a] + bias + Q[a1] + Q[a2] ----
        const long long tb = (long long)t * TILE_M * DDIM;
        #pragma unroll
        for (int a = 0; a < AGENTS; a++) {
            const int a1 = (a + 1) % 3, a2 = (a + 2) % 3;
            const float* sxa = sx + a * TILE_M * SXT_STRIDE;
            float* oa = out + (long long)a * nB * DDIM + tb;
            #pragma unroll
            for (int ni = 0; ni < 4; ni++) {
                const int c0 = wn * 32 + ni * 8 + 2 * tig;
                const int r0 = wm * 16 + gid;
                float2 xv0 = *(const float2*)(sxa + r0 * SXT_STRIDE + c0);
                float2 o0;
                o0.x = xv0.x + br[ni][0] + acc[a1][ni][0] + acc[a2][ni][0];
                o0.y = xv0.y + br[ni][1] + acc[a1][ni][1] + acc[a2][ni][1];
                *(float2*)(oa + (long long)r0 * DDIM + c0) = o0;

                const int r1 = r0 + 8;
                float2 xv1 = *(const float2*)(sxa + r1 * SXT_STRIDE + c0);
                float2 o1;
                o1.x = xv1.x + br[ni][0] + acc[a1][ni][2] + acc[a2][ni][2];
                o1.y = xv1.y + br[ni][1] + acc[a1][ni][3] + acc[a2][ni][3];
                *(float2*)(oa + (long long)r1 * DDIM + c0) = o1;
            }
        }
        __syncthreads();   // everyone done reading stage s

        // refill stage s with tile t + STAGES*grid
        prefetch_tile(smem + s * STAGE_FLOATS, X,
                      t + STAGES * (int)gridDim.x, ntiles, nB, tid);
    }
}

extern "C" void kernel_launch(void* const* d_in, const int* in_sizes, int n_in,
                              void* d_out, int out_size)
{
    const float* X    = (const float*)d_in[0];   // [3, B, 128]
    const float* W    = (const float*)d_in[1];   // [128, 128]
    const float* bias = (const float*)d_in[2];   // [128]
    float* out = (float*)d_out;

    const int nB     = in_sizes[0] / (AGENTS * DDIM);   // 524288
    const int ntiles = nB / TILE_M;                     // 16384

    int dev = 0, nsm = 148;
    cudaGetDevice(&dev);
    cudaDeviceGetAttribute(&nsm, cudaDevAttrMultiProcessorCount, dev);

    cudaFuncSetAttribute(comm_layer_kernel,
                         cudaFuncAttributeMaxDynamicSharedMemorySize, SMEM_BYTES);
    comm_layer_kernel<<<nsm, NTH, SMEM_BYTES>>>(X, W, bias, out, nB, ntiles);
}

// round 16
// speedup vs baseline: 1.1131x; 1.0014x over previous
#include <cuda_runtime.h>
#include <cstdint>

// CommunicationLayer: out[a] = x[a] + b + ((sum_j x[j] - x[a]) / 2) @ W
// A=3, D=128, fp32. Persistent-CTA TF32 mma.sync kernel, cp.async pipelined.
//
// R14: W fragments hoisted into REGISTERS (128 regs/thread, loaded once per
// kernel) -> zero B-operand smem traffic in the main loop. A operands use raw
// fp32 bits (HW truncates to tf32); 0.5 folded into W (exact).

#define AGENTS  3
#define DDIM    128
#define TILE_M  32
#define NTH     256
#define STAGES  3

#define SXT_STRIDE   132                              // padded x-tile row (floats)
#define STAGE_FLOATS (AGENTS * TILE_M * SXT_STRIDE)   // 12672
#define SW_STRIDE    136                              // padded W row (floats)
#define SW_FLOATS    (DDIM * SW_STRIDE)               // 17408
#define SW_OFF       (STAGES * STAGE_FLOATS)          // 38016
#define SB_OFF       (SW_OFF + SW_FLOATS)
#define SMEM_FLOATS  (SB_OFF + DDIM)
#define SMEM_BYTES   (SMEM_FLOATS * 4)                // 222208

__device__ __forceinline__ uint32_t f2tf32(float f) {
    uint32_t r;
    asm("cvt.rna.tf32.f32 %0, %1;" : "=r"(r) : "f"(f));
    return r;
}

__device__ __forceinline__ void mma_tf32(float c[4], const uint32_t a[4], const uint32_t b0, const uint32_t b1) {
    asm volatile(
        "mma.sync.aligned.m16n8k8.row.col.f32.tf32.tf32.f32 "
        "{%0,%1,%2,%3}, {%4,%5,%6,%7}, {%8,%9}, {%0,%1,%2,%3};"
        : "+f"(c[0]), "+f"(c[1]), "+f"(c[2]), "+f"(c[3])
        : "r"(a[0]), "r"(a[1]), "r"(a[2]), "r"(a[3]),
          "r"(b0), "r"(b1));
}

__device__ __forceinline__ void cp_async16(float* dst_smem, const float* src_gmem) {
    uint32_t d = (uint32_t)__cvta_generic_to_shared(dst_smem);
    asm volatile("cp.async.cg.shared.global [%0], [%1], 16;\n" :: "r"(d), "l"(src_gmem));
}

// Prefetch one full x tile (3 agents x 32 x 128 fp32) into stage s.
__device__ __forceinline__ void prefetch_tile(float* stage, const float* __restrict__ X,
                                              int t, int ntiles, int nB, int tid) {
    if (t < ntiles) {
        const long long tb = (long long)t * TILE_M * DDIM;
        #pragma unroll
        for (int q = 0; q < 12; q++) {
            int idx = tid + q * NTH;            // 0..3071 float4s
            int a   = idx >> 10;                // 1024 float4 per agent tile
            int rem = idx & 1023;
            int r   = rem >> 5;                 // 32 float4 per row
            int c   = (rem & 31) << 2;          // float col
            const float* src = X + (long long)a * nB * DDIM + tb + r * DDIM + c;
            float*       dst = stage + a * TILE_M * SXT_STRIDE + r * SXT_STRIDE + c;
            cp_async16(dst, src);
        }
    }
    asm volatile("cp.async.commit_group;\n" ::: "memory");
}

__global__ __launch_bounds__(NTH, 1)
void comm_layer_kernel(const float* __restrict__ X,    // [3, B, 128]
                       const float* __restrict__ W,    // [128, 128]
                       const float* __restrict__ bias, // [128]
                       float* __restrict__ out,        // [3, B, 128]
                       int nB, int ntiles)
{
    extern __shared__ float smem[];
    float* sW = smem + SW_OFF;     // tf32(0.5*W), [128][136] (used only at init)
    float* sB = smem + SB_OFF;

    const int tid  = threadIdx.x;
    const int warp = tid >> 5, lane = tid & 31;
    const int wm   = warp >> 2;    // 0..1 : 16-row m block
    const int wn   = warp & 3;     // 0..3 : 32-col n block
    const int gid  = lane >> 2;    // 0..7
    const int tig  = lane & 3;     // 0..3

    // ---- prologue: kick off the first STAGES tile prefetches immediately ----
    #pragma unroll
    for (int s = 0; s < STAGES; s++)
        prefetch_tile(smem + s * STAGE_FLOATS, X,
                      blockIdx.x + s * (int)gridDim.x, ntiles, nB, tid);

    // ---- stage W (scaled by 0.5, tf32 RNA-rounded) + bias into smem ----
    for (int i = tid; i < (DDIM * DDIM) / 4; i += NTH) {
        float4 v = __ldg(((const float4*)W) + i);
        int r = i >> 5, c = (i & 31) << 2;
        float* d = sW + r * SW_STRIDE + c;
        d[0] = __uint_as_float(f2tf32(0.5f * v.x));
        d[1] = __uint_as_float(f2tf32(0.5f * v.y));
        d[2] = __uint_as_float(f2tf32(0.5f * v.z));
        d[3] = __uint_as_float(f2tf32(0.5f * v.w));
    }
    if (tid < DDIM) sB[tid] = bias[tid];
    __syncthreads();

    // ---- hoist ALL B fragments for this thread into registers (once) ----
    // breg[k-step][ni][pair]: W[k0+tig][col], W[k0+tig+4][col], col = wn*32+ni*8+gid
    uint32_t breg[16][4][2];
    {
        const float* wb = sW + tig * SW_STRIDE + wn * 32 + gid;
        #pragma unroll
        for (int kk = 0; kk < 16; kk++) {
            #pragma unroll
            for (int ni = 0; ni < 4; ni++) {
                const float* pw = wb + (kk * 8) * SW_STRIDE + ni * 8;
                breg[kk][ni][0] = __float_as_uint(pw[0]);
                breg[kk][ni][1] = __float_as_uint(pw[4 * SW_STRIDE]);
            }
        }
    }

    // bias hoisted into registers (fixed columns per thread)
    float br[4][2];
    #pragma unroll
    for (int ni = 0; ni < 4; ni++) {
        int c0 = wn * 32 + ni * 8 + 2 * tig;
        br[ni][0] = sB[c0];
        br[ni][1] = sB[c0 + 1];
    }

    // per-thread A fragment base offset
    const int a_base = (wm * 16 + gid) * SXT_STRIDE + tig;   // + j*tile + k0

    // ---- main pipelined loop over tiles ----
    int iter = 0;
    for (int t = blockIdx.x; t < ntiles; t += (int)gridDim.x, iter++) {
        const int s = iter % STAGES;
        asm volatile("cp.async.wait_group %0;\n" :: "n"(STAGES - 1) : "memory");
        __syncthreads();

        const float* sx = smem + s * STAGE_FLOATS;

        // Q[j] = x[j] @ (0.5*W) for j = 0..2, fp32 accumulate.
        // A operands: raw fp32 bits (HW uses top 19 bits => tf32-truncate).
        float acc[AGENTS][4][4];
        #pragma unroll
        for (int j = 0; j < AGENTS; j++)
            #pragma unroll
            for (int ni = 0; ni < 4; ni++)
                #pragma unroll
                for (int e = 0; e < 4; e++)
                    acc[j][ni][e] = 0.0f;

        #pragma unroll
        for (int kk = 0; kk < 16; kk++) {
            const int k0 = kk * 8;
            #pragma unroll
            for (int j = 0; j < AGENTS; j++) {
                const float* pm = sx + j * TILE_M * SXT_STRIDE + a_base + k0;
                uint32_t afr[4];
                afr[0] = __float_as_uint(pm[0]);
                afr[1] = __float_as_uint(pm[8 * SXT_STRIDE]);
                afr[2] = __float_as_uint(pm[4]);
                afr[3] = __float_as_uint(pm[8 * SXT_STRIDE + 4]);
                #pragma unroll
                for (int ni = 0; ni < 4; ni++)
                    mma_tf32(acc[j][ni], afr, breg[kk][ni][0], breg[kk][ni][1]);
            }
        }

        // ---- epilogue: out[a] = x[a] + bias + Q[a1] + Q[a2] ----
        const long long tb = (long long)t * TILE_M * DDIM;
        #pragma unroll
        for (int a = 0; a < AGENTS; a++) {
            const int a1 = (a + 1) % 3, a2 = (a + 2) % 3;
            const float* sxa = sx + a * TILE_M * SXT_STRIDE;
            float* oa = out + (long long)a * nB * DDIM + tb;
            #pragma unroll
            for (int ni = 0; ni < 4; ni++) {
                const int c0 = wn * 32 + ni * 8 + 2 * tig;
                const int r0 = wm * 16 + gid;
                float2 xv0 = *(const float2*)(sxa + r0 * SXT_STRIDE + c0);
                float2 o0;
                o0.x = xv0.x + br[ni][0] + acc[a1][ni][0] + acc[a2][ni][0];
                o0.y = xv0.y + br[ni][1] + acc[a1][ni][1] + acc[a2][ni][1];
                *(float2*)(oa + (long long)r0 * DDIM + c0) = o0;

                const int r1 = r0 + 8;
                float2 xv1 = *(const float2*)(sxa + r1 * SXT_STRIDE + c0);
                float2 o1;
                o1.x = xv1.x + br[ni][0] + acc[a1][ni][2] + acc[a2][ni][2];
                o1.y = xv1.y + br[ni][1] + acc[a1][ni][3] + acc[a2][ni][3];
                *(float2*)(oa + (long long)r1 * DDIM + c0) = o1;
            }
        }
        __syncthreads();   // everyone done reading stage s

        // refill stage s with tile t + STAGES*grid
        prefetch_tile(smem + s * STAGE_FLOATS, X,
                      t + STAGES * (int)gridDim.x, ntiles, nB, tid);
    }
}

extern "C" void kernel_launch(void* const* d_in, const int* in_sizes, int n_in,
                              void* d_out, int out_size)
{
    const float* X    = (const float*)d_in[0];   // [3, B, 128]
    const float* W    = (const float*)d_in[1];   // [128, 128]
    const float* bias = (const float*)d_in[2];   // [128]
    float* out = (float*)d_out;

    const int nB     = in_sizes[0] / (AGENTS * DDIM);   // 524288
    const int ntiles = nB / TILE_M;                     // 16384

    int dev = 0, nsm = 148;
    cudaGetDevice(&dev);
    cudaDeviceGetAttribute(&nsm, cudaDevAttrMultiProcessorCount, dev);

    cudaFuncSetAttribute(comm_layer_kernel,
                         cudaFuncAttributeMaxDynamicSharedMemorySize, SMEM_BYTES);
    comm_layer_kernel<<<nsm, NTH, SMEM_BYTES>>>(X, W, bias, out, nB, ntiles);
}